// round 8
// baseline (speedup 1.0000x reference)
#include <cuda_runtime.h>
#include <cstdint>

#define BB 16
#define T_STEPS 20
#define NT 3777
#define GRID_CONV 592

// ---------------- persistent device state ----------------
__device__ float g_v [BB*3*32*32];
__device__ float g_s [BB*3*32*32];
__device__ float g_m1[BB*64*32*32];
__device__ float g_o1[BB*64*32*32];
__device__ float g_o1p[BB*64*16*16];
__device__ float g_m2[BB*128*16*16];
__device__ float g_o2[BB*128*16*16];
__device__ float g_m3[BB*128*16*16];
__device__ float g_o3[BB*128*16*16];
__device__ float g_f [BB*8192];
__device__ float g_m4[BB*1024];
__device__ float g_o4[BB*1024];
__device__ float g_m5[BB*1024];
__device__ float g_o5[BB*1024];
__device__ float g_mo[BB*10];
__device__ int   g_tick;

// ---------------- partial-sum slabs (deterministic K-split) ----------------
__device__ float g_c1s[BB*64*32*32];        // conv1 raw out
__device__ float g_s2 [4][BB*128*16*16];    // conv2: 4 cin-splits
__device__ float g_s3 [8][BB*128*16*16];    // conv3: 8 cin-splits
__device__ float g_s4 [32][BB*1024];        // fc1: 32 k-splits
__device__ float g_s5 [4][BB*1024];         // fc2: 4 k-splits

// ---------------- f32x2 helpers ----------------
__device__ __forceinline__ uint64_t pk2(float lo, float hi) {
    uint64_t r; asm("mov.b64 %0, {%1, %2};" : "=l"(r) : "f"(lo), "f"(hi)); return r;
}
__device__ __forceinline__ void upk(uint64_t v, float& lo, float& hi) {
    asm("mov.b64 {%0, %1}, %2;" : "=f"(lo), "=f"(hi) : "l"(v));
}
__device__ __forceinline__ void fma2(uint64_t& d, uint64_t a, uint64_t b) {
    asm("fma.rn.f32x2 %0, %1, %2, %0;" : "+l"(d) : "l"(a), "l"(b));
}

// ---------------- zero state ----------------
__global__ void zero_state() {
    int n  = gridDim.x * blockDim.x;
    int i0 = blockIdx.x * blockDim.x + threadIdx.x;
    for (int i = i0; i < BB*3*32*32;   i += n) { g_v[i] = 0.f; g_s[i] = 0.f; }
    for (int i = i0; i < BB*64*32*32;  i += n) { g_m1[i] = 0.f; g_o1[i] = 0.f; g_c1s[i] = 0.f; }
    for (int i = i0; i < BB*128*16*16; i += n) {
        g_m2[i] = 0.f; g_o2[i] = 0.f; g_m3[i] = 0.f; g_o3[i] = 0.f;
        #pragma unroll
        for (int k = 0; k < 4; k++) g_s2[k][i] = 0.f;
        #pragma unroll
        for (int k = 0; k < 8; k++) g_s3[k][i] = 0.f;
    }
    for (int i = i0; i < BB*1024; i += n) {
        g_m4[i] = 0.f; g_o4[i] = 0.f; g_m5[i] = 0.f; g_o5[i] = 0.f;
        #pragma unroll
        for (int k = 0; k < 32; k++) g_s4[k][i] = 0.f;
        #pragma unroll
        for (int k = 0; k < 4;  k++) g_s5[k][i] = 0.f;
    }
    for (int i = i0; i < BB*10; i += n) g_mo[i] = 0.f;
}

// keeps ncu -s 5 aligned onto a conv_step launch
__global__ void nop_k() {}

// ---------------- per-step spike kernel: membrane completion + thresholds ----------------
__global__ void __launch_bounds__(256) spike_step(const float* __restrict__ x) {
    int i = blockIdx.x * 256 + threadIdx.x;
    if (i == 0) g_tick = 0;
    if (i < 49152) {
        float v = g_v[i] + x[i];
        v = v - g_s[i];
        g_v[i] = v;
        g_s[i] = (v > 1.0f) ? 1.0f : 0.0f;
    } else if (i < 311296) {
        int p  = i - 49152;                  // (B*64, 16, 16) pooled
        int px = p & 15, py = (p >> 4) & 15, bc = p >> 8;
        int base = (bc*32 + py*2)*32 + px*2;
        float sum = 0.f;
        #pragma unroll
        for (int dy = 0; dy < 2; dy++)
            #pragma unroll
            for (int dx = 0; dx < 2; dx++) {
                int idx = base + dy*32 + dx;
                float m = (g_m1[idx] + g_c1s[idx]) - g_o1[idx];
                float o = (m > 1.0f) ? 1.0f : 0.0f;
                g_m1[idx] = m;
                g_o1[idx] = o;
                sum += o;
            }
        g_o1p[p] = sum * 0.25f;
    } else if (i < 835584) {
        int p = i - 311296;
        float inp = ((g_s2[0][p] + g_s2[1][p]) + g_s2[2][p]) + g_s2[3][p];
        float m = (g_m2[p] + inp) - g_o2[p];
        g_m2[p] = m;
        g_o2[p] = (m > 1.0f) ? 1.0f : 0.0f;
    } else if (i < 966656) {
        int p  = i - 835584;                 // (B*128, 8, 8) pooled
        int px = p & 7, py = (p >> 3) & 7, bc = p >> 6;
        int base = (bc*16 + py*2)*16 + px*2;
        float sum = 0.f;
        #pragma unroll
        for (int dy = 0; dy < 2; dy++)
            #pragma unroll
            for (int dx = 0; dx < 2; dx++) {
                int idx = base + dy*16 + dx;
                float inp = 0.f;
                #pragma unroll
                for (int k = 0; k < 8; k++) inp += g_s3[k][idx];
                float m = (g_m3[idx] + inp) - g_o3[idx];
                float o = (m > 1.0f) ? 1.0f : 0.0f;
                g_m3[idx] = m;
                g_o3[idx] = o;
                sum += o;
            }
        int b = bc >> 7, c = bc & 127;
        g_f[b*8192 + c*64 + py*8 + px] = sum * 0.25f;
    } else if (i < 983040) {
        int p = i - 966656;
        float inp = 0.f;
        #pragma unroll 8
        for (int k = 0; k < 32; k++) inp += g_s4[k][p];
        float m = (g_m4[p] + inp) - g_o4[p];
        g_m4[p] = m;
        g_o4[p] = (m > 1.0f) ? 1.0f : 0.0f;
    } else if (i < 999424) {
        int p = i - 983040;
        float inp = ((g_s5[0][p] + g_s5[1][p]) + g_s5[2][p]) + g_s5[3][p];
        float m = (g_m5[p] + inp) - g_o5[p];
        g_m5[p] = m;
        g_o5[p] = (m > 1.0f) ? 1.0f : 0.0f;
    }
}

// ---------------- conv tile: 16 oc x 8 rows x 16 cols x 16 cin ----------------
// R4 thread layout: 8 warps; warp = oc-pair; lane: yl = sg&7, xq = sg>>3.
// Thread = 2 oc x 4 px.
// Input fill: R4's proven pattern (linear idx, consecutive banks, no conflicts).
// Weight fill: linear float4 stores (consecutive tids -> consecutive float4s,
// conflict-free by construction). Layout: (c,dy)-grouped 8-float dup blocks
// [w0,w0,w1,w1,w2,w2,-,-] -> compute reads 2x LDS.128 + 2x LDS.64 broadcast.
// Input smem: 16c x 10 rows x 20 cols, skew +6 floats on odd rows: per half-warp
// the 16 LDS.64 unit-indices are distinct mod 16 -> conflict-free.
#define IN_PITCH 208
__device__ __forceinline__ void conv_tile(
    const float* __restrict__ in, const float* __restrict__ W,
    float* __restrict__ slab, int CIN, int cb, int b, int oc0, int y0, float* sm)
{
    float* in_s = sm;                 // 16*208 = 3328 floats
    float* w_s  = sm + 3328;          // 16c*3dy*16oc*8 = 6144 floats
    const int tid = threadIdx.x;
    const int wid = tid >> 5;         // oc-pair 0..7 (warp-uniform)
    const int sg  = tid & 31;
    const int yl  = sg & 7;
    const int xb  = (sg >> 3) * 4;

    // ---- input fill: 16c x 10 rows x 20 cols (halo + zero pad), skewed ----
    for (int idx = tid; idx < 3200; idx += 256) {
        int c  = idx / 200; int r = idx - c*200;
        int yy = r / 20;    int xx = r - yy*20;
        int gy = y0 + yy - 1, gx = xx - 1;
        float v = 0.f;
        if ((unsigned)gy < 16u && (unsigned)gx < 16u)
            v = in[((b*CIN + cb + c)*16 + gy)*16 + gx];
        in_s[c*IN_PITCH + yy*20 + 6*(yy & 1) + xx] = v;
    }
    // ---- weight fill: linear float4 writes, conflict-free ----
    {
        float4* wp = (float4*)w_s;
        #pragma unroll
        for (int k = 0; k < 6; k++) {
            int i  = tid + k*256;             // 0..1535
            int h  = i & 1;
            int oc = (i >> 1) & 15;
            int cd = i >> 5;                  // c*3 + dy, 0..47
            int c  = cd / 3, dy = cd - c*3;
            const float* src = W + (oc0 + oc)*CIN*9 + (cb + c)*9 + dy*3;
            float4 val;
            if (h == 0) { float w0 = src[0], w1 = src[1]; val = make_float4(w0, w0, w1, w1); }
            else        { float w2 = src[2];              val = make_float4(w2, w2, 0.f, 0.f); }
            wp[i] = val;
        }
    }
    __syncthreads();

    // ---- compute ----
    uint64_t acc[2][2];
    acc[0][0] = acc[0][1] = acc[1][0] = acc[1][1] = pk2(0.f, 0.f);

    const int off0 = (yl    )*20 + 6*((yl    ) & 1) + xb;
    const int off1 = (yl + 1)*20 + 6*((yl + 1) & 1) + xb;
    const int off2 = (yl + 2)*20 + 6*((yl + 2) & 1) + xb;

    const float* cin = in_s;
    const float* wc  = w_s + wid*16;
    #pragma unroll 1
    for (int c = 0; c < 16; c++) {
        #pragma unroll
        for (int dy = 0; dy < 3; dy++) {
            const int off = (dy == 0) ? off0 : (dy == 1) ? off1 : off2;
            const uint64_t* rp = (const uint64_t*)(cin + off);
            uint64_t E0 = rp[0], E1 = rp[1], E2 = rp[2];
            float a0,a1,a2,a3,a4,a5;
            upk(E0,a0,a1); upk(E1,a2,a3); upk(E2,a4,a5);
            uint64_t D0 = pk2(a1,a2), D1 = pk2(a3,a4);
            const float* wd = wc + dy*128;
            ulonglong2 wwA = *(const ulonglong2*)(wd);       // oc even: (w0,w0),(w1,w1)
            uint64_t   WA2 = *(const uint64_t*)(wd + 4);     // (w2,w2)
            ulonglong2 wwB = *(const ulonglong2*)(wd + 8);   // oc odd
            uint64_t   WB2 = *(const uint64_t*)(wd + 12);
            fma2(acc[0][0], E0, wwA.x); fma2(acc[0][0], D0, wwA.y); fma2(acc[0][0], E1, WA2);
            fma2(acc[0][1], E1, wwA.x); fma2(acc[0][1], D1, wwA.y); fma2(acc[0][1], E2, WA2);
            fma2(acc[1][0], E0, wwB.x); fma2(acc[1][0], D0, wwB.y); fma2(acc[1][0], E1, WB2);
            fma2(acc[1][1], E1, wwB.x); fma2(acc[1][1], D1, wwB.y); fma2(acc[1][1], E2, WB2);
        }
        cin += IN_PITCH;
        wc  += 384;
    }
    #pragma unroll
    for (int q = 0; q < 2; q++) {
        int oc = oc0 + wid*2 + q;
        float4 r;
        upk(acc[q][0], r.x, r.y);
        upk(acc[q][1], r.z, r.w);
        *(float4*)&slab[((b*128 + oc)*16 + (y0 + yl))*16 + xb] = r;
    }
}

// ---------------- conv1 tile (3 in-ch, 32x32), 4 units of 256 ----------------
__device__ __forceinline__ void conv1_tile(
    const float* __restrict__ s, const float* __restrict__ W1,
    float* __restrict__ slab, int tile, float* sm)
{
    int tid = threadIdx.x;
    for (int idx = tid; idx < 1728; idx += 256) sm[idx] = W1[idx];
    __syncthreads();
    #pragma unroll 1
    for (int u4 = 0; u4 < 4; u4++) {
        int u   = (tile*4 + u4)*256 + tid;
        int row = u >> 2;
        int xb  = (u & 3) * 8;
        int b   = row >> 11;
        int oc  = (row >> 5) & 63;
        int y   = row & 31;
        float acc[8];
        #pragma unroll
        for (int i = 0; i < 8; i++) acc[i] = 0.f;
        #pragma unroll
        for (int c = 0; c < 3; c++) {
            #pragma unroll
            for (int dy = 0; dy < 3; dy++) {
                int gy = y + dy - 1;
                if ((unsigned)gy >= 32u) continue;
                const float* srow = s + ((b*3 + c)*32 + gy)*32;
                float iv[10];
                #pragma unroll
                for (int t = 0; t < 10; t++) {
                    int gx = xb + t - 1;
                    iv[t] = ((unsigned)gx < 32u) ? srow[gx] : 0.f;
                }
                float w[3];
                #pragma unroll
                for (int dx = 0; dx < 3; dx++) w[dx] = sm[oc*27 + c*9 + dy*3 + dx];
                #pragma unroll
                for (int i = 0; i < 8; i++)
                    #pragma unroll
                    for (int dx = 0; dx < 3; dx++)
                        acc[i] += iv[i + dx] * w[dx];
            }
        }
        int base = ((b*64 + oc)*32 + y)*32 + xb;
        #pragma unroll
        for (int i = 0; i < 8; i++) slab[base + i] = acc[i];
    }
}

// ---------------- FC tile: out[b,j] = A[b,k0:k0+256] . W[j,k0:k0+256] ----------------
__device__ __forceinline__ void fc_tile(
    const float* __restrict__ A, const float* __restrict__ W,
    float* __restrict__ out, int K, int j0, int k0, float* sm)
{
    float* fs = sm;          // [16][64]
    float* ws = sm + 1024;   // [64][65]
    int tid = threadIdx.x;
    int tj  = tid & 31;
    int tb  = tid >> 5;
    float acc[2][2] = {{0.f,0.f},{0.f,0.f}};
    #pragma unroll 1
    for (int kc = k0; kc < k0 + 256; kc += 64) {
        __syncthreads();
        for (int idx = tid; idx < 1024; idx += 256) {
            int bb = idx >> 6, kk = idx & 63;
            fs[idx] = A[bb*K + kc + kk];
        }
        for (int idx = tid; idx < 4096; idx += 256) {
            int jl = idx >> 6, kk = idx & 63;
            ws[jl*65 + kk] = W[(j0 + jl)*K + kc + kk];
        }
        __syncthreads();
        #pragma unroll 4
        for (int kk = 0; kk < 64; kk++) {
            float w0 = ws[(tj*2    )*65 + kk];
            float w1 = ws[(tj*2 + 1)*65 + kk];
            float f0 = fs[ tb      *64 + kk];
            float f1 = fs[(tb + 8) *64 + kk];
            acc[0][0] += w0*f0;  acc[0][1] += w0*f1;
            acc[1][0] += w1*f0;  acc[1][1] += w1*f1;
        }
    }
    #pragma unroll
    for (int q = 0; q < 2; q++)
        #pragma unroll
        for (int r = 0; r < 2; r++)
            out[(tb + r*8)*1024 + (j0 + tj*2 + q)] = acc[q][r];
}

// ---------------- fc3: mo += o5 @ L3^T (single tile, deterministic) ----------------
__device__ __forceinline__ void fc3_part(
    const float* __restrict__ o5, const float* __restrict__ L3, float* __restrict__ mo)
{
    int t = threadIdx.x;
    if (t >= 160) return;
    int b = t / 10, j = t - b*10;
    const float* a = o5 + b*1024;
    const float* w = L3 + j*1024;
    float acc = 0.f;
    #pragma unroll 4
    for (int k = 0; k < 1024; k++) acc += a[k]*w[k];
    mo[t] += acc;
}

// ---------------- fat per-step kernel: work queue over 3777 uniform tiles ----------------
__global__ void __launch_bounds__(256, 4) conv_step(
    const float* __restrict__ W1, const float* __restrict__ W2,
    const float* __restrict__ W3, const float* __restrict__ L1,
    const float* __restrict__ L2, const float* __restrict__ L3)
{
    __shared__ __align__(16) float sm[9472];
    __shared__ int s_tile;
    for (;;) {
        __syncthreads();
        if (threadIdx.x == 0) s_tile = atomicAdd(&g_tick, 1);
        __syncthreads();
        int t = s_tile;
        if (t >= NT) return;
        if (t == 0) {
            fc3_part(g_o5, L3, g_mo);
        } else if (t < 2049) {               // conv3: 16b x 8ocg x 2yb x 8ks
            int i = t - 1;
            int ks = i & 7, yb = (i >> 3) & 1, ocg = (i >> 4) & 7, b = i >> 7;
            conv_tile(g_o2, W3, &g_s3[ks][0], 128, ks*16, b, ocg*16, yb*8, sm);
        } else if (t < 3073) {               // conv2: 16b x 8ocg x 2yb x 4ks
            int i = t - 2049;
            int ks = i & 3, yb = (i >> 2) & 1, ocg = (i >> 3) & 7, b = i >> 6;
            conv_tile(g_o1p, W2, &g_s2[ks][0], 64, ks*16, b, ocg*16, yb*8, sm);
        } else if (t < 3585) {               // fc1: 16jg x 32ks
            int i = t - 3073;
            int jg = i & 15, ks = i >> 4;
            fc_tile(g_f, L1, &g_s4[ks][0], 8192, jg*64, ks*256, sm);
        } else if (t < 3713) {               // conv1: 128 tiles x 4 units
            conv1_tile(g_s, W1, g_c1s, t - 3585, sm);
        } else {                             // fc2: 16jg x 4ks
            int i = t - 3713;
            int jg = i & 15, ks = i >> 4;
            fc_tile(g_o4, L2, &g_s5[ks][0], 1024, jg*64, ks*256, sm);
        }
    }
}

__global__ void write_out(float* __restrict__ out) {
    int t = threadIdx.x;
    if (t < 160) out[t] = g_mo[t];
}

extern "C" void kernel_launch(void* const* d_in, const int* in_sizes, int n_in,
                              void* d_out, int out_size)
{
    const float* x  = (const float*)d_in[0];
    const float* W1 = (const float*)d_in[1];
    const float* W2 = (const float*)d_in[2];
    const float* W3 = (const float*)d_in[3];
    const float* L1 = (const float*)d_in[4];
    const float* L2 = (const float*)d_in[5];
    const float* L3 = (const float*)d_in[6];

    zero_state<<<512, 256>>>();
    nop_k<<<1, 32>>>();
    for (int t = 0; t < T_STEPS; t++) {
        spike_step<<<3904, 256>>>(x);
        conv_step<<<GRID_CONV, 256>>>(W1, W2, W3, L1, L2, L3);
    }
    write_out<<<1, 192>>>((float*)d_out);
}

// round 9
// speedup vs baseline: 1.3914x; 1.3914x over previous
#include <cuda_runtime.h>
#include <cuda_bf16.h>
#include <cstdint>

#define BB 16
#define T_STEPS 20
#define NT 961
#define GRID_CONV 592
#define SMEM_BYTES 55296

// ---------------- persistent device state ----------------
__device__ float g_v [BB*3*32*32];
__device__ float g_s [BB*3*32*32];
__device__ float g_m1[BB*64*32*32];     // NCHW
__device__ float g_o1[BB*64*32*32];     // NCHW
__device__ float g_m2[BB*16*16*128];    // NHWC
__device__ float g_o2[BB*16*16*128];    // NHWC
__device__ float g_m3[BB*16*16*128];    // NHWC
__device__ float g_o3[BB*16*16*128];    // NHWC
__device__ float g_f [BB*8192];
__device__ float g_m4[BB*1024];
__device__ float g_o4[BB*1024];
__device__ float g_m5[BB*1024];
__device__ float g_o5[BB*1024];
__device__ float g_mo[BB*10];
__device__ int   g_tick;

// conv slabs (single, NHWC) + fc K-split slabs
__device__ float g_c1s[BB*64*32*32];    // conv1 raw out, NCHW
__device__ float g_s2 [BB*16*16*128];   // conv2 out, NHWC
__device__ float g_s3 [BB*16*16*128];   // conv3 out, NHWC
__device__ float g_s4 [32][BB*1024];    // fc1: 32 k-splits
__device__ float g_s5 [4][BB*1024];     // fc2: 4 k-splits

// bf16 activations, channel-last, zero halo [b][18][18][C]
__device__ __nv_bfloat16 g_a2[BB*18*18*64];    // conv2 input (pooled conv1)
__device__ __nv_bfloat16 g_a3[BB*18*18*128];   // conv3 input (conv2 spikes)

// bf16 3-term split weights, linear stream [term][dydx][c][oc]
__device__ __nv_bfloat16 g_w2t[3*9*64*128];
__device__ __nv_bfloat16 g_w3t[3*9*128*128];

// ---------------- zero state ----------------
__global__ void zero_state() {
    int n  = gridDim.x * blockDim.x;
    int i0 = blockIdx.x * blockDim.x + threadIdx.x;
    for (int i = i0; i < BB*3*32*32;   i += n) { g_v[i] = 0.f; g_s[i] = 0.f; }
    for (int i = i0; i < BB*64*32*32;  i += n) { g_m1[i] = 0.f; g_o1[i] = 0.f; g_c1s[i] = 0.f; }
    for (int i = i0; i < BB*16*16*128; i += n) {
        g_m2[i] = 0.f; g_o2[i] = 0.f; g_m3[i] = 0.f; g_o3[i] = 0.f;
        g_s2[i] = 0.f; g_s3[i] = 0.f;
    }
    for (int i = i0; i < BB*18*18*64;  i += n) g_a2[i] = __float2bfloat16(0.f);
    for (int i = i0; i < BB*18*18*128; i += n) g_a3[i] = __float2bfloat16(0.f);
    for (int i = i0; i < BB*1024; i += n) {
        g_m4[i] = 0.f; g_o4[i] = 0.f; g_m5[i] = 0.f; g_o5[i] = 0.f;
        #pragma unroll
        for (int k = 0; k < 32; k++) g_s4[k][i] = 0.f;
        #pragma unroll
        for (int k = 0; k < 4;  k++) g_s5[k][i] = 0.f;
    }
    for (int i = i0; i < BB*10; i += n) g_mo[i] = 0.f;
}

// ---------------- weight preprocessing: 3-term bf16 split ----------------
// layout: [term][dydx][c][oc], linear stream for the GEMM B stager.
__global__ void prep_weights(const float* __restrict__ W2, const float* __restrict__ W3) {
    int i = blockIdx.x * blockDim.x + threadIdx.x;
    float w; int dst;
    if (i < 147456) {                       // conv3: 9 dydx * 128 c * 128 oc
        int oc = i & 127, c = (i >> 7) & 127, dydx = i >> 14;
        w = W3[(oc*128 + c)*9 + dydx];
        dst = dydx*16384 + c*128 + oc;
        __nv_bfloat16 h = __float2bfloat16_rn(w);
        float r1 = w - __bfloat162float(h);
        __nv_bfloat16 m = __float2bfloat16_rn(r1);
        float r2 = r1 - __bfloat162float(m);
        __nv_bfloat16 l = __float2bfloat16_rn(r2);
        g_w3t[dst] = h; g_w3t[147456 + dst] = m; g_w3t[294912 + dst] = l;
    } else if (i < 221184) {                // conv2: 9 * 64 * 128
        int j = i - 147456;
        int oc = j & 127, c = (j >> 7) & 63, dydx = j >> 13;
        w = W2[(oc*64 + c)*9 + dydx];
        dst = dydx*8192 + c*128 + oc;
        __nv_bfloat16 h = __float2bfloat16_rn(w);
        float r1 = w - __bfloat162float(h);
        __nv_bfloat16 m = __float2bfloat16_rn(r1);
        float r2 = r1 - __bfloat162float(m);
        __nv_bfloat16 l = __float2bfloat16_rn(r2);
        g_w2t[dst] = h; g_w2t[73728 + dst] = m; g_w2t[147456 + dst] = l;
    }
}

// ---------------- per-step spike kernel ----------------
__global__ void __launch_bounds__(256) spike_step(const float* __restrict__ x) {
    int i = blockIdx.x * 256 + threadIdx.x;
    if (i == 0) g_tick = 0;
    if (i < 49152) {
        float v = g_v[i] + x[i];
        v = v - g_s[i];
        g_v[i] = v;
        g_s[i] = (v > 1.0f) ? 1.0f : 0.0f;
    } else if (i < 311296) {
        // conv1 membranes (NCHW) + pool -> a2 (bf16 halo NHWC)
        int p  = i - 49152;                  // over (b,64c,16py,16px)
        int px = p & 15, py = (p >> 4) & 15, bc = p >> 8;
        int b = bc >> 6, c = bc & 63;
        int base = (bc*32 + py*2)*32 + px*2;
        float sum = 0.f;
        #pragma unroll
        for (int dy = 0; dy < 2; dy++)
            #pragma unroll
            for (int dx = 0; dx < 2; dx++) {
                int idx = base + dy*32 + dx;
                float m = (g_m1[idx] + g_c1s[idx]) - g_o1[idx];
                float o = (m > 1.0f) ? 1.0f : 0.0f;
                g_m1[idx] = m;
                g_o1[idx] = o;
                sum += o;
            }
        g_a2[((b*18 + py + 1)*18 + px + 1)*64 + c] = __float2bfloat16(sum * 0.25f);
    } else if (i < 835584) {
        // conv2 membranes, NHWC; spikes -> a3 (bf16 halo)
        int p = i - 311296;
        int c = p & 127, xx = (p >> 7) & 15, y = (p >> 11) & 15, b = p >> 15;
        float m = (g_m2[p] + g_s2[p]) - g_o2[p];
        float o = (m > 1.0f) ? 1.0f : 0.0f;
        g_m2[p] = m;
        g_o2[p] = o;
        g_a3[((b*18 + y + 1)*18 + xx + 1)*128 + c] = __float2bfloat16(o);
    } else if (i < 966656) {
        // conv3 membranes NHWC + pool -> f (fp32, NCHW-flatten order)
        int p = i - 835584;                  // over (b, 8py, 8px, 128c)
        int c = p & 127, px = (p >> 7) & 7, py = (p >> 10) & 7, b = p >> 13;
        float sum = 0.f;
        #pragma unroll
        for (int dy = 0; dy < 2; dy++)
            #pragma unroll
            for (int dx = 0; dx < 2; dx++) {
                int idx = ((b*16 + 2*py + dy)*16 + 2*px + dx)*128 + c;
                float m = (g_m3[idx] + g_s3[idx]) - g_o3[idx];
                float o = (m > 1.0f) ? 1.0f : 0.0f;
                g_m3[idx] = m;
                g_o3[idx] = o;
                sum += o;
            }
        g_f[b*8192 + c*64 + py*8 + px] = sum * 0.25f;
    } else if (i < 983040) {
        int p = i - 966656;
        float inp = 0.f;
        #pragma unroll 8
        for (int k = 0; k < 32; k++) inp += g_s4[k][p];
        float m = (g_m4[p] + inp) - g_o4[p];
        g_m4[p] = m;
        g_o4[p] = (m > 1.0f) ? 1.0f : 0.0f;
    } else if (i < 999424) {
        int p = i - 983040;
        float inp = ((g_s5[0][p] + g_s5[1][p]) + g_s5[2][p]) + g_s5[3][p];
        float m = (g_m5[p] + inp) - g_o5[p];
        g_m5[p] = m;
        g_o5[p] = (m > 1.0f) ? 1.0f : 0.0f;
    }
}

// ---------------- tensor-core conv tile ----------------
// out[b, y0..y0+1, 0..15, 0..127] += sum over (term, dy, dx, c) of
//   act[b][y+dy][x+dx][c] * Wt[term][dydx][c][oc]
// 8 warps: wm = wid&1 (y-row), wn = wid>>1 (32-oc group); warp = m16 x n32.
// A slab smem: 4 rows x 18 px x (CIN+8) bf16 (pad -> ldmatrix conflict-free).
// B: k64 x 128 stage (row pad 136), cp.async double-buffered linear stream.
__device__ __forceinline__ void gemm_conv_tile(
    const __nv_bfloat16* __restrict__ act, const __nv_bfloat16* __restrict__ Wt,
    float* __restrict__ slab, int CIN, int H, int SH, int b, int y0, float* smf)
{
    const int PS = CIN + 8;
    __nv_bfloat16* As = (__nv_bfloat16*)smf;
    __nv_bfloat16* Bs = As + 4*18*PS;
    unsigned as_u = (unsigned)__cvta_generic_to_shared(As);
    unsigned bs_u = (unsigned)__cvta_generic_to_shared(Bs);
    const int tid = threadIdx.x, wid = tid >> 5, lane = tid & 31;
    const int wm = wid & 1, wn = wid >> 1;
    const int mr = lane & 15, kh = lane >> 4;

    // prefetch B stage 0
    const __nv_bfloat16* bptr = Wt;
    #pragma unroll
    for (int j = 0; j < 4; j++) {
        int i = tid + j*256;
        unsigned d = bs_u + (i >> 4)*272 + (i & 15)*16;
        asm volatile("cp.async.cg.shared.global [%0], [%1], 16;\n"
                     :: "r"(d), "l"(bptr + i*8) : "memory");
    }
    asm volatile("cp.async.commit_group;\n" ::: "memory");

    // fill A slab (4 halo rows x 18 px x CIN), px stride padded to PS
    {
        const int cpp = CIN >> 3;             // 16B chunks per pixel
        const int CPR = 18 * cpp;             // chunks per row
        const int TOT = 4 * CPR;
        for (int i = tid; i < TOT; i += 256) {
            int r  = i / CPR; int rr = i - r*CPR;
            int px = rr >> SH; int inner = rr & (cpp - 1);
            uint4 v = *(const uint4*)(act + (((b*18 + y0 + r)*18 + px)*CIN) + inner*8);
            *(uint4*)(As + (r*18 + px)*PS + inner*8) = v;
        }
    }

    float d0[4], d1[4], d2[4], d3[4];
    #pragma unroll
    for (int nb = 0; nb < 4; nb++) { d0[nb]=0.f; d1[nb]=0.f; d2[nb]=0.f; d3[nb]=0.f; }

    int buf = 0;
    const int nst = 27 * H;
    int s = 0;
    #pragma unroll 1
    for (int t3 = 0; t3 < 3; t3++)
    for (int dy = 0; dy < 3; dy++)
    for (int dx = 0; dx < 3; dx++) {
        unsigned a_base = as_u + (unsigned)((((wm + dy)*18 + mr + dx)*PS + kh*8) * 2);
        #pragma unroll 1
        for (int h = 0; h < H; h++, s++) {
            const __nv_bfloat16* nxt = bptr + 8192;
            if (s != nst - 1) {
                #pragma unroll
                for (int j = 0; j < 4; j++) {
                    int i = tid + j*256;
                    unsigned dd = bs_u + (buf ^ 1)*17408 + (i >> 4)*272 + (i & 15)*16;
                    asm volatile("cp.async.cg.shared.global [%0], [%1], 16;\n"
                                 :: "r"(dd), "l"(nxt + i*8) : "memory");
                }
                asm volatile("cp.async.commit_group;\n" ::: "memory");
                asm volatile("cp.async.wait_group 1;\n" ::: "memory");
            } else {
                asm volatile("cp.async.wait_group 0;\n" ::: "memory");
            }
            __syncthreads();
            unsigned bb = bs_u + buf*17408;
            unsigned arow = a_base + h*128;
            #pragma unroll
            for (int k16 = 0; k16 < 4; k16++) {
                unsigned r0, r1, r2, r3;
                asm volatile("ldmatrix.sync.aligned.m8n8.x4.shared.b16 {%0,%1,%2,%3}, [%4];\n"
                             : "=r"(r0), "=r"(r1), "=r"(r2), "=r"(r3)
                             : "r"(arow + k16*32));
                unsigned brow = bb + (unsigned)((k16*16 + mr)*272 + wn*64);
                #pragma unroll
                for (int nb = 0; nb < 4; nb++) {
                    unsigned p0, p1;
                    asm volatile("ldmatrix.sync.aligned.m8n8.x2.trans.shared.b16 {%0,%1}, [%2];\n"
                                 : "=r"(p0), "=r"(p1) : "r"(brow + nb*16));
                    asm volatile("mma.sync.aligned.m16n8k16.row.col.f32.bf16.bf16.f32 "
                                 "{%0,%1,%2,%3}, {%4,%5,%6,%7}, {%8,%9}, {%0,%1,%2,%3};\n"
                                 : "+f"(d0[nb]), "+f"(d1[nb]), "+f"(d2[nb]), "+f"(d3[nb])
                                 : "r"(r0), "r"(r1), "r"(r2), "r"(r3), "r"(p0), "r"(p1));
                }
            }
            __syncthreads();
            bptr = nxt; buf ^= 1;
        }
    }
    // store accumulators: frag row = x, cols = oc
    int xr = lane >> 2, nc0 = (lane & 3)*2;
    float* obase = slab + (((b*16 + y0 + wm)*16 + xr)*128 + wn*32 + nc0);
    #pragma unroll
    for (int nb = 0; nb < 4; nb++) {
        *(float2*)(obase + nb*8)        = make_float2(d0[nb], d1[nb]);
        *(float2*)(obase + nb*8 + 1024) = make_float2(d2[nb], d3[nb]);
    }
}

// ---------------- conv1 tile (3 in-ch, 32x32), 4 units of 256 ----------------
__device__ __forceinline__ void conv1_tile(
    const float* __restrict__ s, const float* __restrict__ W1,
    float* __restrict__ slab, int tile, float* sm)
{
    int tid = threadIdx.x;
    for (int idx = tid; idx < 1728; idx += 256) sm[idx] = W1[idx];
    __syncthreads();
    #pragma unroll 1
    for (int u4 = 0; u4 < 4; u4++) {
        int u   = (tile*4 + u4)*256 + tid;
        int row = u >> 2;
        int xb  = (u & 3) * 8;
        int b   = row >> 11;
        int oc  = (row >> 5) & 63;
        int y   = row & 31;
        float acc[8];
        #pragma unroll
        for (int i = 0; i < 8; i++) acc[i] = 0.f;
        #pragma unroll
        for (int c = 0; c < 3; c++) {
            #pragma unroll
            for (int dy = 0; dy < 3; dy++) {
                int gy = y + dy - 1;
                if ((unsigned)gy >= 32u) continue;
                const float* srow = s + ((b*3 + c)*32 + gy)*32;
                float iv[10];
                #pragma unroll
                for (int t = 0; t < 10; t++) {
                    int gx = xb + t - 1;
                    iv[t] = ((unsigned)gx < 32u) ? srow[gx] : 0.f;
                }
                float w[3];
                #pragma unroll
                for (int dx = 0; dx < 3; dx++) w[dx] = sm[oc*27 + c*9 + dy*3 + dx];
                #pragma unroll
                for (int i = 0; i < 8; i++)
                    #pragma unroll
                    for (int dx = 0; dx < 3; dx++)
                        acc[i] += iv[i + dx] * w[dx];
            }
        }
        int base = ((b*64 + oc)*32 + y)*32 + xb;
        #pragma unroll
        for (int i = 0; i < 8; i++) slab[base + i] = acc[i];
    }
}

// ---------------- FC tile: out[b,j] = A[b,k0:k0+256] . W[j,k0:k0+256] ----------------
__device__ __forceinline__ void fc_tile(
    const float* __restrict__ A, const float* __restrict__ W,
    float* __restrict__ out, int K, int j0, int k0, float* sm)
{
    float* fs = sm;          // [16][64]
    float* ws = sm + 1024;   // [64][65]
    int tid = threadIdx.x;
    int tj  = tid & 31;
    int tb  = tid >> 5;
    float acc[2][2] = {{0.f,0.f},{0.f,0.f}};
    #pragma unroll 1
    for (int kc = k0; kc < k0 + 256; kc += 64) {
        __syncthreads();
        for (int idx = tid; idx < 1024; idx += 256) {
            int bb = idx >> 6, kk = idx & 63;
            fs[idx] = A[bb*K + kc + kk];
        }
        for (int idx = tid; idx < 4096; idx += 256) {
            int jl = idx >> 6, kk = idx & 63;
            ws[jl*65 + kk] = W[(j0 + jl)*K + kc + kk];
        }
        __syncthreads();
        #pragma unroll 4
        for (int kk = 0; kk < 64; kk++) {
            float w0 = ws[(tj*2    )*65 + kk];
            float w1 = ws[(tj*2 + 1)*65 + kk];
            float f0 = fs[ tb      *64 + kk];
            float f1 = fs[(tb + 8) *64 + kk];
            acc[0][0] += w0*f0;  acc[0][1] += w0*f1;
            acc[1][0] += w1*f0;  acc[1][1] += w1*f1;
        }
    }
    #pragma unroll
    for (int q = 0; q < 2; q++)
        #pragma unroll
        for (int r = 0; r < 2; r++)
            out[(tb + r*8)*1024 + (j0 + tj*2 + q)] = acc[q][r];
}

// ---------------- fc3: mo += o5 @ L3^T ----------------
__device__ __forceinline__ void fc3_part(
    const float* __restrict__ o5, const float* __restrict__ L3, float* __restrict__ mo)
{
    int t = threadIdx.x;
    if (t >= 160) return;
    int b = t / 10, j = t - b*10;
    const float* a = o5 + b*1024;
    const float* w = L3 + j*1024;
    float acc = 0.f;
    #pragma unroll 4
    for (int k = 0; k < 1024; k++) acc += a[k]*w[k];
    mo[t] += acc;
}

// ---------------- fat per-step kernel: work queue over 961 tiles ----------------
__global__ void __launch_bounds__(256, 4) conv_step(
    const float* __restrict__ W1, const float* __restrict__ L1,
    const float* __restrict__ L2, const float* __restrict__ L3)
{
    extern __shared__ float smf[];
    __shared__ int s_tile;
    for (;;) {
        __syncthreads();
        if (threadIdx.x == 0) s_tile = atomicAdd(&g_tick, 1);
        __syncthreads();
        int t = s_tile;
        if (t >= NT) return;
        if (t < 128) {                       // conv3 TC: 16b x 8 y-pairs
            int b = t >> 3, y0 = (t & 7)*2;
            gemm_conv_tile(g_a3, g_w3t, g_s3, 128, 2, 4, b, y0, smf);
        } else if (t < 256) {                // conv2 TC
            int i = t - 128;
            int b = i >> 3, y0 = (i & 7)*2;
            gemm_conv_tile(g_a2, g_w2t, g_s2, 64, 1, 3, b, y0, smf);
        } else if (t < 768) {                // fc1: 16jg x 32ks
            int i = t - 256;
            int jg = i & 15, ks = i >> 4;
            fc_tile(g_f, L1, &g_s4[ks][0], 8192, jg*64, ks*256, smf);
        } else if (t < 896) {                // conv1: 128 tiles x 4 units
            conv1_tile(g_s, W1, g_c1s, t - 768, smf);
        } else if (t < 960) {                // fc2: 16jg x 4ks
            int i = t - 896;
            int jg = i & 15, ks = i >> 4;
            fc_tile(g_o4, L2, &g_s5[ks][0], 1024, jg*64, ks*256, smf);
        } else {                             // fc3
            fc3_part(g_o5, L3, g_mo);
        }
    }
}

__global__ void write_out(float* __restrict__ out) {
    int t = threadIdx.x;
    if (t < 160) out[t] = g_mo[t];
}

extern "C" void kernel_launch(void* const* d_in, const int* in_sizes, int n_in,
                              void* d_out, int out_size)
{
    const float* x  = (const float*)d_in[0];
    const float* W1 = (const float*)d_in[1];
    const float* W2 = (const float*)d_in[2];
    const float* W3 = (const float*)d_in[3];
    const float* L1 = (const float*)d_in[4];
    const float* L2 = (const float*)d_in[5];
    const float* L3 = (const float*)d_in[6];

    cudaFuncSetAttribute(conv_step, cudaFuncAttributeMaxDynamicSharedMemorySize, SMEM_BYTES);

    zero_state<<<512, 256>>>();
    prep_weights<<<864, 256>>>(W2, W3);
    for (int t = 0; t < T_STEPS; t++) {
        spike_step<<<3904, 256>>>(x);
        conv_step<<<GRID_CONV, 256, SMEM_BYTES>>>(W1, L1, L2, L3);
    }
    write_out<<<1, 192>>>((float*)d_out);
}

// round 10
// speedup vs baseline: 1.4615x; 1.0504x over previous
#include <cuda_runtime.h>
#include <cuda_bf16.h>
#include <cstdint>

#define BB 16
#define T_STEPS 20
#define NT 833
#define GRID_CONV 592
#define SMEM_BYTES 64512

// ---------------- persistent device state ----------------
__device__ float g_v [BB*3*32*32];
__device__ float g_s [BB*3*32*32];
__device__ float g_m1[BB*64*32*32];     // NCHW
__device__ float g_o1[BB*64*32*32];     // NCHW
__device__ float g_m2[BB*16*16*128];    // NHWC
__device__ float g_o2[BB*16*16*128];    // NHWC
__device__ float g_m3[BB*16*16*128];    // NHWC
__device__ float g_o3[BB*16*16*128];    // NHWC
__device__ float g_f [BB*8192];
__device__ float g_m4[BB*1024];
__device__ float g_o4[BB*1024];
__device__ float g_m5[BB*1024];
__device__ float g_o5[BB*1024];
__device__ float g_mo[BB*10];
__device__ int   g_tick;

// conv slabs (single, NHWC) + fc K-split slabs
__device__ float g_c1s[BB*64*32*32];    // conv1 raw out, NCHW
__device__ float g_s2 [BB*16*16*128];   // conv2 out, NHWC
__device__ float g_s3 [BB*16*16*128];   // conv3 out, NHWC
__device__ float g_s4 [32][BB*1024];    // fc1: 32 k-splits
__device__ float g_s5 [4][BB*1024];     // fc2: 4 k-splits

// bf16 activations, channel-last, zero halo [b][18][18][C]
__device__ __nv_bfloat16 g_a2[BB*18*18*64];    // conv2 input (pooled conv1)
__device__ __nv_bfloat16 g_a3[BB*18*18*128];   // conv3 input (conv2 spikes)

// bf16 3-term split weights, linear stream [term][dydx][c][oc]
__device__ __nv_bfloat16 g_w2t[3*9*64*128];
__device__ __nv_bfloat16 g_w3t[3*9*128*128];

// ---------------- zero state ----------------
__global__ void zero_state() {
    int n  = gridDim.x * blockDim.x;
    int i0 = blockIdx.x * blockDim.x + threadIdx.x;
    for (int i = i0; i < BB*3*32*32;   i += n) { g_v[i] = 0.f; g_s[i] = 0.f; }
    for (int i = i0; i < BB*64*32*32;  i += n) { g_m1[i] = 0.f; g_o1[i] = 0.f; g_c1s[i] = 0.f; }
    for (int i = i0; i < BB*16*16*128; i += n) {
        g_m2[i] = 0.f; g_o2[i] = 0.f; g_m3[i] = 0.f; g_o3[i] = 0.f;
        g_s2[i] = 0.f; g_s3[i] = 0.f;
    }
    for (int i = i0; i < BB*18*18*64;  i += n) g_a2[i] = __float2bfloat16(0.f);
    for (int i = i0; i < BB*18*18*128; i += n) g_a3[i] = __float2bfloat16(0.f);
    for (int i = i0; i < BB*1024; i += n) {
        g_m4[i] = 0.f; g_o4[i] = 0.f; g_m5[i] = 0.f; g_o5[i] = 0.f;
        #pragma unroll
        for (int k = 0; k < 32; k++) g_s4[k][i] = 0.f;
        #pragma unroll
        for (int k = 0; k < 4;  k++) g_s5[k][i] = 0.f;
    }
    for (int i = i0; i < BB*10; i += n) g_mo[i] = 0.f;
}

// ---------------- weight preprocessing: 3-term bf16 split ----------------
__global__ void prep_weights(const float* __restrict__ W2, const float* __restrict__ W3) {
    int i = blockIdx.x * blockDim.x + threadIdx.x;
    float w; int dst;
    if (i < 147456) {                       // conv3: 9 dydx * 128 c * 128 oc
        int oc = i & 127, c = (i >> 7) & 127, dydx = i >> 14;
        w = W3[(oc*128 + c)*9 + dydx];
        dst = dydx*16384 + c*128 + oc;
        __nv_bfloat16 h = __float2bfloat16_rn(w);
        float r1 = w - __bfloat162float(h);
        __nv_bfloat16 m = __float2bfloat16_rn(r1);
        float r2 = r1 - __bfloat162float(m);
        __nv_bfloat16 l = __float2bfloat16_rn(r2);
        g_w3t[dst] = h; g_w3t[147456 + dst] = m; g_w3t[294912 + dst] = l;
    } else if (i < 221184) {                // conv2: 9 * 64 * 128
        int j = i - 147456;
        int oc = j & 127, c = (j >> 7) & 63, dydx = j >> 13;
        w = W2[(oc*64 + c)*9 + dydx];
        dst = dydx*8192 + c*128 + oc;
        __nv_bfloat16 h = __float2bfloat16_rn(w);
        float r1 = w - __bfloat162float(h);
        __nv_bfloat16 m = __float2bfloat16_rn(r1);
        float r2 = r1 - __bfloat162float(m);
        __nv_bfloat16 l = __float2bfloat16_rn(r2);
        g_w2t[dst] = h; g_w2t[73728 + dst] = m; g_w2t[147456 + dst] = l;
    }
}

// ---------------- per-step spike kernel ----------------
__global__ void __launch_bounds__(256) spike_step(const float* __restrict__ x) {
    int i = blockIdx.x * 256 + threadIdx.x;
    if (i == 0) g_tick = 0;
    if (i < 49152) {
        float v = g_v[i] + x[i];
        v = v - g_s[i];
        g_v[i] = v;
        g_s[i] = (v > 1.0f) ? 1.0f : 0.0f;
    } else if (i < 311296) {
        int p  = i - 49152;                  // (b,64c,16py,16px)
        int px = p & 15, py = (p >> 4) & 15, bc = p >> 8;
        int b = bc >> 6, c = bc & 63;
        int base = (bc*32 + py*2)*32 + px*2;
        float sum = 0.f;
        #pragma unroll
        for (int dy = 0; dy < 2; dy++)
            #pragma unroll
            for (int dx = 0; dx < 2; dx++) {
                int idx = base + dy*32 + dx;
                float m = (g_m1[idx] + g_c1s[idx]) - g_o1[idx];
                float o = (m > 1.0f) ? 1.0f : 0.0f;
                g_m1[idx] = m;
                g_o1[idx] = o;
                sum += o;
            }
        g_a2[((b*18 + py + 1)*18 + px + 1)*64 + c] = __float2bfloat16(sum * 0.25f);
    } else if (i < 835584) {
        int p = i - 311296;
        int c = p & 127, xx = (p >> 7) & 15, y = (p >> 11) & 15, b = p >> 15;
        float m = (g_m2[p] + g_s2[p]) - g_o2[p];
        float o = (m > 1.0f) ? 1.0f : 0.0f;
        g_m2[p] = m;
        g_o2[p] = o;
        g_a3[((b*18 + y + 1)*18 + xx + 1)*128 + c] = __float2bfloat16(o);
    } else if (i < 966656) {
        int p = i - 835584;                  // (b, 8py, 8px, 128c)
        int c = p & 127, px = (p >> 7) & 7, py = (p >> 10) & 7, b = p >> 13;
        float sum = 0.f;
        #pragma unroll
        for (int dy = 0; dy < 2; dy++)
            #pragma unroll
            for (int dx = 0; dx < 2; dx++) {
                int idx = ((b*16 + 2*py + dy)*16 + 2*px + dx)*128 + c;
                float m = (g_m3[idx] + g_s3[idx]) - g_o3[idx];
                float o = (m > 1.0f) ? 1.0f : 0.0f;
                g_m3[idx] = m;
                g_o3[idx] = o;
                sum += o;
            }
        g_f[b*8192 + c*64 + py*8 + px] = sum * 0.25f;
    } else if (i < 983040) {
        int p = i - 966656;
        float inp = 0.f;
        #pragma unroll 8
        for (int k = 0; k < 32; k++) inp += g_s4[k][p];
        float m = (g_m4[p] + inp) - g_o4[p];
        g_m4[p] = m;
        g_o4[p] = (m > 1.0f) ? 1.0f : 0.0f;
    } else if (i < 999424) {
        int p = i - 983040;
        float inp = ((g_s5[0][p] + g_s5[1][p]) + g_s5[2][p]) + g_s5[3][p];
        float m = (g_m5[p] + inp) - g_o5[p];
        g_m5[p] = m;
        g_o5[p] = (m > 1.0f) ? 1.0f : 0.0f;
    }
}

// ---------------- tensor-core conv tile (M=64) ----------------
// out[b, y0..y0+3, 0..15, 0..127] += sum over (term,dy,dx,c) of
//   act[b][y+dy][x+dx][c] * Wt[term][dydx][c][oc]
// 8 warps: wm = wid&3 (y-row 0..3), wn = (wid>>2)&1 (64-oc half).
// Warp = m16 (16 px of row y0+wm) x n64.
// A slab smem: 6 rows x 18 px x (CIN+8) bf16. B: k64 x 128 double-buffered.
__device__ __forceinline__ void gemm_conv_tile(
    const __nv_bfloat16* __restrict__ act, const __nv_bfloat16* __restrict__ Wt,
    float* __restrict__ slab, int CIN, int H, int SH, int b, int y0, float* smf)
{
    const int PS = CIN + 8;
    __nv_bfloat16* As = (__nv_bfloat16*)smf;
    __nv_bfloat16* Bs = As + 6*18*PS;
    unsigned as_u = (unsigned)__cvta_generic_to_shared(As);
    unsigned bs_u = (unsigned)__cvta_generic_to_shared(Bs);
    const int tid = threadIdx.x, wid = tid >> 5, lane = tid & 31;
    const int wm = wid & 3, wn = (wid >> 2) & 1;
    const int mr = lane & 15, kh = lane >> 4;

    // prefetch B stage 0
    const __nv_bfloat16* bptr = Wt;
    #pragma unroll
    for (int j = 0; j < 4; j++) {
        int i = tid + j*256;
        unsigned d = bs_u + (i >> 4)*272 + (i & 15)*16;
        asm volatile("cp.async.cg.shared.global [%0], [%1], 16;\n"
                     :: "r"(d), "l"(bptr + i*8) : "memory");
    }
    asm volatile("cp.async.commit_group;\n" ::: "memory");

    // fill A slab (6 halo rows x 18 px x CIN), px stride padded to PS
    {
        const int cpp = CIN >> 3;             // 16B chunks per pixel
        const int CPR = 18 * cpp;             // chunks per row
        const int TOT = 6 * CPR;
        for (int i = tid; i < TOT; i += 256) {
            int r  = i / CPR; int rr = i - r*CPR;
            int px = rr >> SH; int inner = rr & (cpp - 1);
            uint4 v = *(const uint4*)(act + (((b*18 + y0 + r)*18 + px)*CIN) + inner*8);
            *(uint4*)(As + (r*18 + px)*PS + inner*8) = v;
        }
    }

    float d0[8], d1[8], d2[8], d3[8];
    #pragma unroll
    for (int nb = 0; nb < 8; nb++) { d0[nb]=0.f; d1[nb]=0.f; d2[nb]=0.f; d3[nb]=0.f; }

    int buf = 0;
    const int nst = 27 * H;
    int s = 0;
    #pragma unroll 1
    for (int t3 = 0; t3 < 3; t3++)
    for (int dy = 0; dy < 3; dy++)
    for (int dx = 0; dx < 3; dx++) {
        unsigned a_base = as_u + (unsigned)((((wm + dy)*18 + mr + dx)*PS + kh*8) * 2);
        #pragma unroll 1
        for (int h = 0; h < H; h++, s++) {
            const __nv_bfloat16* nxt = bptr + 8192;
            if (s != nst - 1) {
                #pragma unroll
                for (int j = 0; j < 4; j++) {
                    int i = tid + j*256;
                    unsigned dd = bs_u + (buf ^ 1)*17408 + (i >> 4)*272 + (i & 15)*16;
                    asm volatile("cp.async.cg.shared.global [%0], [%1], 16;\n"
                                 :: "r"(dd), "l"(nxt + i*8) : "memory");
                }
                asm volatile("cp.async.commit_group;\n" ::: "memory");
                asm volatile("cp.async.wait_group 1;\n" ::: "memory");
            } else {
                asm volatile("cp.async.wait_group 0;\n" ::: "memory");
            }
            __syncthreads();
            unsigned bb = bs_u + buf*17408;
            unsigned arow = a_base + h*128;
            #pragma unroll
            for (int k16 = 0; k16 < 4; k16++) {
                unsigned r0, r1, r2, r3;
                asm volatile("ldmatrix.sync.aligned.m8n8.x4.shared.b16 {%0,%1,%2,%3}, [%4];\n"
                             : "=r"(r0), "=r"(r1), "=r"(r2), "=r"(r3)
                             : "r"(arow + k16*32));
                unsigned brow = bb + (unsigned)((k16*16 + mr)*272 + wn*128);
                #pragma unroll
                for (int nb = 0; nb < 8; nb++) {
                    unsigned p0, p1;
                    asm volatile("ldmatrix.sync.aligned.m8n8.x2.trans.shared.b16 {%0,%1}, [%2];\n"
                                 : "=r"(p0), "=r"(p1) : "r"(brow + nb*16));
                    asm volatile("mma.sync.aligned.m16n8k16.row.col.f32.bf16.bf16.f32 "
                                 "{%0,%1,%2,%3}, {%4,%5,%6,%7}, {%8,%9}, {%0,%1,%2,%3};\n"
                                 : "+f"(d0[nb]), "+f"(d1[nb]), "+f"(d2[nb]), "+f"(d3[nb])
                                 : "r"(r0), "r"(r1), "r"(r2), "r"(r3), "r"(p0), "r"(p1));
                }
            }
            __syncthreads();
            bptr = nxt; buf ^= 1;
        }
    }
    // store accumulators: frag row = x, cols = oc
    int xr = lane >> 2, nc0 = (lane & 3)*2;
    float* obase = slab + (((b*16 + y0 + wm)*16 + xr)*128 + wn*64 + nc0);
    #pragma unroll
    for (int nb = 0; nb < 8; nb++) {
        *(float2*)(obase + nb*8)        = make_float2(d0[nb], d1[nb]);
        *(float2*)(obase + nb*8 + 1024) = make_float2(d2[nb], d3[nb]);
    }
}

// ---------------- conv1 tile (3 in-ch, 32x32), 4 units of 256 ----------------
__device__ __forceinline__ void conv1_tile(
    const float* __restrict__ s, const float* __restrict__ W1,
    float* __restrict__ slab, int tile, float* sm)
{
    int tid = threadIdx.x;
    for (int idx = tid; idx < 1728; idx += 256) sm[idx] = W1[idx];
    __syncthreads();
    #pragma unroll 1
    for (int u4 = 0; u4 < 4; u4++) {
        int u   = (tile*4 + u4)*256 + tid;
        int row = u >> 2;
        int xb  = (u & 3) * 8;
        int b   = row >> 11;
        int oc  = (row >> 5) & 63;
        int y   = row & 31;
        float acc[8];
        #pragma unroll
        for (int i = 0; i < 8; i++) acc[i] = 0.f;
        #pragma unroll
        for (int c = 0; c < 3; c++) {
            #pragma unroll
            for (int dy = 0; dy < 3; dy++) {
                int gy = y + dy - 1;
                if ((unsigned)gy >= 32u) continue;
                const float* srow = s + ((b*3 + c)*32 + gy)*32;
                float iv[10];
                #pragma unroll
                for (int t = 0; t < 10; t++) {
                    int gx = xb + t - 1;
                    iv[t] = ((unsigned)gx < 32u) ? srow[gx] : 0.f;
                }
                float w[3];
                #pragma unroll
                for (int dx = 0; dx < 3; dx++) w[dx] = sm[oc*27 + c*9 + dy*3 + dx];
                #pragma unroll
                for (int i = 0; i < 8; i++)
                    #pragma unroll
                    for (int dx = 0; dx < 3; dx++)
                        acc[i] += iv[i + dx] * w[dx];
            }
        }
        int base = ((b*64 + oc)*32 + y)*32 + xb;
        #pragma unroll
        for (int i = 0; i < 8; i++) slab[base + i] = acc[i];
    }
}

// ---------------- FC tile: out[b,j] = A[b,k0:k0+256] . W[j,k0:k0+256] ----------------
__device__ __forceinline__ void fc_tile(
    const float* __restrict__ A, const float* __restrict__ W,
    float* __restrict__ out, int K, int j0, int k0, float* sm)
{
    float* fs = sm;          // [16][64]
    float* ws = sm + 1024;   // [64][65]
    int tid = threadIdx.x;
    int tj  = tid & 31;
    int tb  = tid >> 5;
    float acc[2][2] = {{0.f,0.f},{0.f,0.f}};
    #pragma unroll 1
    for (int kc = k0; kc < k0 + 256; kc += 64) {
        __syncthreads();
        for (int idx = tid; idx < 1024; idx += 256) {
            int bb = idx >> 6, kk = idx & 63;
            fs[idx] = A[bb*K + kc + kk];
        }
        for (int idx = tid; idx < 4096; idx += 256) {
            int jl = idx >> 6, kk = idx & 63;
            ws[jl*65 + kk] = W[(j0 + jl)*K + kc + kk];
        }
        __syncthreads();
        #pragma unroll 4
        for (int kk = 0; kk < 64; kk++) {
            float w0 = ws[(tj*2    )*65 + kk];
            float w1 = ws[(tj*2 + 1)*65 + kk];
            float f0 = fs[ tb      *64 + kk];
            float f1 = fs[(tb + 8) *64 + kk];
            acc[0][0] += w0*f0;  acc[0][1] += w0*f1;
            acc[1][0] += w1*f0;  acc[1][1] += w1*f1;
        }
    }
    #pragma unroll
    for (int q = 0; q < 2; q++)
        #pragma unroll
        for (int r = 0; r < 2; r++)
            out[(tb + r*8)*1024 + (j0 + tj*2 + q)] = acc[q][r];
}

// ---------------- fc3: mo += o5 @ L3^T ----------------
__device__ __forceinline__ void fc3_part(
    const float* __restrict__ o5, const float* __restrict__ L3, float* __restrict__ mo)
{
    int t = threadIdx.x;
    if (t >= 160) return;
    int b = t / 10, j = t - b*10;
    const float* a = o5 + b*1024;
    const float* w = L3 + j*1024;
    float acc = 0.f;
    #pragma unroll 4
    for (int k = 0; k < 1024; k++) acc += a[k]*w[k];
    mo[t] += acc;
}

// ---------------- fat per-step kernel: work queue over 833 tiles ----------------
__global__ void __launch_bounds__(256, 3) conv_step(
    const float* __restrict__ W1, const float* __restrict__ L1,
    const float* __restrict__ L2, const float* __restrict__ L3)
{
    extern __shared__ float smf[];
    __shared__ int s_tile;
    for (;;) {
        __syncthreads();
        if (threadIdx.x == 0) s_tile = atomicAdd(&g_tick, 1);
        __syncthreads();
        int t = s_tile;
        if (t >= NT) return;
        if (t < 64) {                        // conv3 TC: 16b x 4 y-quads
            int b = t >> 2, y0 = (t & 3)*4;
            gemm_conv_tile(g_a3, g_w3t, g_s3, 128, 2, 4, b, y0, smf);
        } else if (t < 128) {                // conv2 TC
            int i = t - 64;
            int b = i >> 2, y0 = (i & 3)*4;
            gemm_conv_tile(g_a2, g_w2t, g_s2, 64, 1, 3, b, y0, smf);
        } else if (t < 640) {                // fc1: 16jg x 32ks
            int i = t - 128;
            int jg = i & 15, ks = i >> 4;
            fc_tile(g_f, L1, &g_s4[ks][0], 8192, jg*64, ks*256, smf);
        } else if (t < 768) {                // conv1: 128 tiles x 4 units
            conv1_tile(g_s, W1, g_c1s, t - 640, smf);
        } else if (t < 832) {                // fc2: 16jg x 4ks
            int i = t - 768;
            int jg = i & 15, ks = i >> 4;
            fc_tile(g_o4, L2, &g_s5[ks][0], 1024, jg*64, ks*256, smf);
        } else {                             // fc3
            fc3_part(g_o5, L3, g_mo);
        }
    }
}

__global__ void write_out(float* __restrict__ out) {
    int t = threadIdx.x;
    if (t < 160) out[t] = g_mo[t];
}

extern "C" void kernel_launch(void* const* d_in, const int* in_sizes, int n_in,
                              void* d_out, int out_size)
{
    const float* x  = (const float*)d_in[0];
    const float* W1 = (const float*)d_in[1];
    const float* W2 = (const float*)d_in[2];
    const float* W3 = (const float*)d_in[3];
    const float* L1 = (const float*)d_in[4];
    const float* L2 = (const float*)d_in[5];
    const float* L3 = (const float*)d_in[6];

    cudaFuncSetAttribute(conv_step, cudaFuncAttributeMaxDynamicSharedMemorySize, SMEM_BYTES);

    zero_state<<<512, 256>>>();
    prep_weights<<<864, 256>>>(W2, W3);
    for (int t = 0; t < T_STEPS; t++) {
        spike_step<<<3904, 256>>>(x);
        conv_step<<<GRID_CONV, 256, SMEM_BYTES>>>(W1, L1, L2, L3);
    }
    write_out<<<1, 192>>>((float*)d_out);
}